// round 13
// baseline (speedup 1.0000x reference)
#include <cuda_runtime.h>
#include <cuda_fp16.h>
#include <math.h>
#include <stdint.h>

// ---------------------------------------------------------------------------
//   base_feat: (32,256,512,4,4) f32 -> 8192 samples of (512,16)
//   rois:(8192,4) i32  w1:(512,256) b1:(256) w2:(256,128) b2:(128)
//   wl:(2048,1024) bl:(1024)  out:(8192,1024) f32
//
// feat[o,i,j] = b2[o] + S1[o]*(i,j odd) + Z[o,a,b]*((i,j) in {3,7}^2)
// Z = X(32768x512) @ W^T(128x512), pool fused in epilogue.
// out = leakyrelu(P(8192x2048) @ wl + bl).
// fp16 mma.sync m16n8k16, fp32 accumulate.
// gemm3: BM=128/BN=256/BK=64, 4-stage deep pipeline (192KB smem).
// wsplit runs as extra blocks of the zgemm launch (fills its idle wave-2 SMs).
// ---------------------------------------------------------------------------

#define NSAMP 8192

__device__ float g_S1[128];
__device__ unsigned short g_X[(size_t)NSAMP * 4 * 512];   // [m=4n+c][k] fp16
__device__ unsigned short g_WZ[128 * 512];                // W^T [o][k]  fp16
__device__ unsigned short g_P[(size_t)NSAMP * 2048];      // P [n][o*16+cell] fp16
__device__ unsigned short g_WT[(size_t)1024 * 2048];      // wl^T [nn][k] fp16

#define SWZ128(off) ((off) ^ (((off) >> 3) & 0x70))

__device__ __forceinline__ unsigned short f2h(float x) {
    return __half_as_ushort(__float2half_rn(x));
}
__device__ __forceinline__ void cp16(uint32_t dst, const void* src) {
    asm volatile("cp.async.cg.shared.global [%0], [%1], 16;"
                 :: "r"(dst), "l"(__cvta_generic_to_global(src)) : "memory");
}
__device__ __forceinline__ void ldm_x4(uint32_t addr, uint32_t& r0, uint32_t& r1,
                                       uint32_t& r2, uint32_t& r3) {
    asm volatile("ldmatrix.sync.aligned.m8n8.x4.shared.b16 {%0,%1,%2,%3}, [%4];"
                 : "=r"(r0), "=r"(r1), "=r"(r2), "=r"(r3) : "r"(addr));
}
__device__ __forceinline__ void mma_f16(float& d0, float& d1, float& d2, float& d3,
                                        uint32_t a0, uint32_t a1, uint32_t a2,
                                        uint32_t a3, uint32_t b0, uint32_t b1) {
    asm volatile("mma.sync.aligned.m16n8k16.row.col.f32.f16.f16.f32 "
                 "{%0,%1,%2,%3}, {%4,%5,%6,%7}, {%8,%9}, {%0,%1,%2,%3};"
                 : "+f"(d0), "+f"(d1), "+f"(d2), "+f"(d3)
                 : "r"(a0), "r"(a1), "r"(a2), "r"(a3), "r"(b0), "r"(b1));
}

// ===== fp16 GEMM building blocks (BK = 64 fp16 = 128B rows) ================
#define B_OFF      16384u
#define STAGE_SZ   32768u
#define NSTAGE     3u

__device__ __forceinline__ void load_chunk_h(
    uint32_t sbase,
    const unsigned short* __restrict__ A, const unsigned short* __restrict__ B,
    int arow0, int brow0, size_t strideA, size_t strideB, int k0, int tid) {
    #pragma unroll
    for (int it = 0; it < 8; ++it) {
        const int g = tid + it * 256;            // 0..2047 (16B units)
        const int isB = g >> 10;
        const int e   = g & 1023;
        const int r   = e >> 3, u = e & 7;       // 128 rows x 8 x 16B
        const uint32_t dst = sbase + (uint32_t)isB * B_OFF
                           + SWZ128((uint32_t)(r * 128 + u * 16));
        const unsigned short* src =
            isB ? (B + (size_t)(brow0 + r) * strideB + k0 + u * 8)
                : (A + (size_t)(arow0 + r) * strideA + k0 + u * 8);
        cp16(dst, src);
    }
}

__device__ __forceinline__ void mma_block_h(uint32_t cur, float acc[4][4][4],
                                            int wm, int wn, int lane) {
    const int lrow = lane & 15;
    const int lcg  = (lane >> 4) * 16;
    #pragma unroll
    for (int ks = 0; ks < 4; ++ks) {
        const int kb = ks * 32 + lcg;
        uint32_t a[4][4], b[4][2];
        #pragma unroll
        for (int mt = 0; mt < 4; ++mt)
            ldm_x4(cur + SWZ128((uint32_t)((wm + mt * 16 + lrow) * 128 + kb)),
                   a[mt][0], a[mt][1], a[mt][2], a[mt][3]);
        #pragma unroll
        for (int q = 0; q < 2; ++q) {
            uint32_t r0, r1, r2, r3;
            ldm_x4(cur + B_OFF + SWZ128((uint32_t)((wn + q * 16 + lrow) * 128 + kb)),
                   r0, r1, r2, r3);
            b[2 * q][0] = r0;     b[2 * q][1] = r2;
            b[2 * q + 1][0] = r1; b[2 * q + 1][1] = r3;
        }
        #pragma unroll
        for (int mt = 0; mt < 4; ++mt)
            #pragma unroll
            for (int nt = 0; nt < 4; ++nt)
                mma_f16(acc[mt][nt][0], acc[mt][nt][1],
                        acc[mt][nt][2], acc[mt][nt][3],
                        a[mt][0], a[mt][1], a[mt][2], a[mt][3],
                        b[nt][0], b[nt][1]);
    }
}

// ---------------------------------------------------------------------------
// Kernel 1 (producers minus wsplit), 256 threads:
//   [0,256):      W = w1 @ w2 -> fp16 g_WZ
//   [256]:        S1 = b1 @ w2
//   [257,2305):   extract centers -> fp16 g_X  (4 samples/block, batched MLP)
// ---------------------------------------------------------------------------
#define S1_B      256
#define XSP_B0    257
#define PREP_GRID 2305

__global__ __launch_bounds__(256) void prep_all(const float* __restrict__ w1,
                                                const float* __restrict__ b1,
                                                const float* __restrict__ w2,
                                                const float* __restrict__ base) {
    __shared__ float w1s[2][256];
    const int b   = blockIdx.x;
    const int tid = threadIdx.x;

    if (b < S1_B) {
        for (int i = tid; i < 512; i += 256)
            ((float*)w1s)[i] = w1[(size_t)b * 512 + i];
        __syncthreads();
        const int kk = tid >> 7, o = tid & 127;
        float acc = 0.f;
        #pragma unroll 4
        for (int c = 0; c < 256; ++c)
            acc = fmaf(w1s[kk][c], w2[c * 128 + o], acc);
        g_WZ[o * 512 + b * 2 + kk] = f2h(acc);
    } else if (b == S1_B) {
        if (tid < 128) {
            float acc = 0.f;
            for (int c = 0; c < 256; ++c) acc = fmaf(b1[c], w2[c * 128 + tid], acc);
            g_S1[tid] = acc;
        }
    } else {
        // --- extract 2x2 centers; all 16 loads batched before any converts ---
        const int n0 = (b - XSP_B0) * 4;
        float4 v1[4][2], v2[4][2];
        #pragma unroll
        for (int s = 0; s < 4; ++s) {
            const float4* src = (const float4*)(base + (size_t)(n0 + s) * 8192);
            #pragma unroll
            for (int i = 0; i < 2; ++i) {
                const int k = tid + i * 256;
                v1[s][i] = __ldcs(&src[k * 4 + 1]);   // f5,f6
                v2[s][i] = __ldcs(&src[k * 4 + 2]);   // f9,f10
            }
        }
        #pragma unroll
        for (int s = 0; s < 4; ++s) {
            #pragma unroll
            for (int i = 0; i < 2; ++i) {
                const int k = tid + i * 256;
                const size_t m0 = (size_t)(4 * (n0 + s)) * 512 + k;
                g_X[m0 + 0 * 512] = f2h(v1[s][i].y);
                g_X[m0 + 1 * 512] = f2h(v1[s][i].z);
                g_X[m0 + 2 * 512] = f2h(v2[s][i].y);
                g_X[m0 + 3 * 512] = f2h(v2[s][i].z);
            }
        }
    }
}

// ---------------------------------------------------------------------------
// Kernel 2: blocks [0,256)  = zgemm (Z = X @ W^T) + fused max-pool epilogue.
//           blocks [256,2304) = wl transpose (fills zgemm's idle wave-2 SMs).
// zgemm: BM=128 (32 samples), BN=128, K=512, BK=64, 3-stage pipeline.
// ---------------------------------------------------------------------------
#define ZG_BLOCKS 256
#define ZG_GRID   (ZG_BLOCKS + 2048)
#define ZCHUNK    8
#define ZS_STRIDE 136
#define SM_ROIS   (NSTAGE * STAGE_SZ)
#define SM_B2     (SM_ROIS + 512u)
#define SM_S1     (SM_B2 + 512u)
#define ZG_SMEM   (SM_S1 + 512u)

__global__ __launch_bounds__(256, 1) void zgemm_kernel(const int* __restrict__ rois,
                                                       const float* __restrict__ b2,
                                                       const float* __restrict__ wl) {
    extern __shared__ __align__(1024) char smem[];
    const int tid  = threadIdx.x;

    if (blockIdx.x >= ZG_BLOCKS) {
        // ---- wsplit: transpose + fp16 one 32x32 tile of wl ----
        float (*t)[33] = (float(*)[33])smem;
        const int w  = blockIdx.x - ZG_BLOCKS;
        const int n0 = (w & 31) * 32, k0 = (w >> 5) * 32;
        const int tx = tid & 31, ty = tid >> 5;   // 32 x 8
        #pragma unroll
        for (int j = 0; j < 4; ++j)
            t[ty + j * 8][tx] = wl[(size_t)(k0 + ty + j * 8) * 1024 + n0 + tx];
        __syncthreads();
        #pragma unroll
        for (int j = 0; j < 4; ++j)
            g_WT[(size_t)(n0 + ty + j * 8) * 2048 + k0 + tx] =
                f2h(t[tx][ty + j * 8]);
        return;
    }

    const uint32_t sb = (uint32_t)__cvta_generic_to_shared(smem);
    const int wid  = tid >> 5, lane = tid & 31;
    const int n0   = blockIdx.x * 32;
    const int bm   = blockIdx.x * 128;
    const int wm   = (wid >> 2) * 64;
    const int wn   = (wid & 3) * 32;

    int4*  rois_s = (int4*)(smem + SM_ROIS);
    float* b2s    = (float*)(smem + SM_B2);
    float* s1s    = (float*)(smem + SM_S1);
    if (tid < 32) rois_s[tid] = ((const int4*)rois)[n0 + tid];
    if (tid >= 128) { b2s[tid - 128] = b2[tid - 128]; s1s[tid - 128] = g_S1[tid - 128]; }

    float acc[4][4][4];
    #pragma unroll
    for (int i = 0; i < 4; ++i)
        #pragma unroll
        for (int j = 0; j < 4; ++j)
            #pragma unroll
            for (int q = 0; q < 4; ++q) acc[i][j][q] = 0.f;

    load_chunk_h(sb, g_X, g_WZ, bm, 0, 512, 512, 0, tid);
    asm volatile("cp.async.commit_group;" ::: "memory");
    load_chunk_h(sb + STAGE_SZ, g_X, g_WZ, bm, 0, 512, 512, 64, tid);
    asm volatile("cp.async.commit_group;" ::: "memory");

    for (int c = 0; c < ZCHUNK; ++c) {
        if (c + 1 < ZCHUNK)
            asm volatile("cp.async.wait_group 1;" ::: "memory");
        else
            asm volatile("cp.async.wait_group 0;" ::: "memory");
        __syncthreads();
        if (c + 2 < ZCHUNK) {
            load_chunk_h(sb + (uint32_t)((c + 2) % 3) * STAGE_SZ,
                         g_X, g_WZ, bm, 0, 512, 512, (c + 2) * 64, tid);
            asm volatile("cp.async.commit_group;" ::: "memory");
        }
        mma_block_h(sb + (uint32_t)(c % 3) * STAGE_SZ, acc, wm, wn, lane);
    }
    __syncthreads();

    float* zs = (float*)smem;
    const int er = lane >> 2, ec = (lane & 3) * 2;
    #pragma unroll
    for (int mt = 0; mt < 4; ++mt)
        #pragma unroll
        for (int nt = 0; nt < 4; ++nt)
            #pragma unroll
            for (int half = 0; half < 2; ++half) {
                const int row = wm + mt * 16 + er + half * 8;
                const int col = wn + nt * 8 + ec;
                *(float2*)&zs[row * ZS_STRIDE + col] =
                    make_float2(acc[mt][nt][half * 2 + 0], acc[mt][nt][half * 2 + 1]);
            }
    __syncthreads();

    #pragma unroll 1
    for (int it = 0; it < 16; ++it) {
        const int pair = tid + it * 256;
        const int n = pair >> 7, o = pair & 127;
        const int4 rr = rois_s[n];
        const float b2o = b2s[o], s1o = s1s[o];
        const float z00 = zs[(4 * n + 0) * ZS_STRIDE + o];
        const float z01 = zs[(4 * n + 1) * ZS_STRIDE + o];
        const float z10 = zs[(4 * n + 2) * ZS_STRIDE + o];
        const float z11 = zs[(4 * n + 3) * ZS_STRIDE + o];

        int y0 = rr.x, x0 = rr.y;
        const int h = rr.z - rr.x, w = rr.w - rr.y;
        const bool inb = (rr.x >= 0 && rr.x < 11 && rr.y >= 0 && rr.y < 11 &&
                          rr.z >= 0 && rr.z < 11 && rr.w >= 0 && rr.w < 11);
        int cat;
        if      (inb && h == 4 && w == 4) cat = 0;
        else if (inb && h == 8 && w == 8) cat = 1;
        else if (inb && h == 4 && w == 8) cat = 2;
        else if (inb && h == 6 && w == 8) cat = 3;
        else { cat = 4; y0 = 1; x0 = 1; }

        auto feval = [&](int i, int j) -> float {
            float v = b2o;
            if ((i & 1) && (j & 1)) {
                v += s1o;
                const bool ia = (i == 3) || (i == 7);
                const bool ja = (j == 3) || (j == 7);
                if (ia && ja)
                    v += (i == 3) ? ((j == 3) ? z00 : z01)
                                  : ((j == 3) ? z10 : z11);
            }
            return v;
        };

        float cell[16];
        if (cat == 0) {
            for (int u = 0; u < 4; ++u)
                for (int v = 0; v < 4; ++v)
                    cell[u * 4 + v] = feval(y0 + u, x0 + v);
        } else if (cat == 1) {
            for (int u = 0; u < 4; ++u)
                for (int v = 0; v < 4; ++v) {
                    const int i0 = y0 + 2 * u, j0 = x0 + 2 * v;
                    cell[u * 4 + v] =
                        fmaxf(fmaxf(feval(i0, j0),     feval(i0, j0 + 1)),
                              fmaxf(feval(i0 + 1, j0), feval(i0 + 1, j0 + 1)));
                }
        } else if (cat == 2) {
            for (int u = 0; u < 4; ++u)
                for (int v = 0; v < 4; ++v) {
                    const int j0 = x0 + 2 * v;
                    cell[u * 4 + v] = fmaxf(feval(y0 + u, j0), feval(y0 + u, j0 + 1));
                }
        } else if (cat == 3) {
            for (int u = 0; u < 4; ++u)
                for (int v = 0; v < 4; ++v) {
                    const int j0 = x0 + 2 * v;
                    float m = -3.402823466e38f;
                    const int r0 = 2 * u - 1, r1 = 2 * u;
                    if (r0 >= 0) m = fmaxf(feval(y0 + r0, j0), feval(y0 + r0, j0 + 1));
                    if (r1 < 6)  m = fmaxf(m, fmaxf(feval(y0 + r1, j0),
                                                    feval(y0 + r1, j0 + 1)));
                    cell[u * 4 + v] = m;
                }
        } else {
            for (int u = 0; u < 4; ++u)
                for (int v = 0; v < 4; ++v) {
                    float m = -3.402823466e38f;
                    for (int di = 0; di < 3; ++di)
                        for (int dj = 0; dj < 3; ++dj)
                            m = fmaxf(m, feval(1 + 2 * u + di, 1 + 2 * v + dj));
                    cell[u * 4 + v] = m;
                }
        }

        __align__(16) unsigned short c16[16];
        #pragma unroll
        for (int i = 0; i < 16; ++i) c16[i] = f2h(cell[i]);
        uint4* pp = (uint4*)&g_P[(size_t)(n0 + n) * 2048 + o * 16];
        pp[0] = ((uint4*)c16)[0];
        pp[1] = ((uint4*)c16)[1];
    }
}

// ---------------------------------------------------------------------------
// Kernel 3: out = leakyrelu(P @ wl + bl), fp16 mma.
// BM=128, BN=256, BK=64, K=2048, 4-stage deep pipeline (192KB smem).
// 8 warps as 2(m) x 4(n), warp tile 64x64.
// ---------------------------------------------------------------------------
#define NCHUNK3   32
#define ST3       49152u    // A 16KB + B 32KB
#define B3_OFF    16384u
#define GEMM_SMEM (4u * ST3)

__device__ __forceinline__ void load_chunk3(uint32_t sbase, int bm, int bn,
                                            int k0, int tid) {
    #pragma unroll
    for (int it = 0; it < 12; ++it) {
        const int g = tid + it * 256;            // 0..3071 (16B units)
        if (g < 1024) {                          // A: 128 rows x 128B
            const int r = g >> 3, u = g & 7;
            cp16(sbase + SWZ128((uint32_t)(r * 128 + u * 16)),
                 &g_P[(size_t)(bm + r) * 2048 + k0 + u * 8]);
        } else {                                 // B: 256 rows x 128B
            const int e = g - 1024;
            const int r = e >> 3, u = e & 7;
            cp16(sbase + B3_OFF + SWZ128((uint32_t)(r * 128 + u * 16)),
                 &g_WT[(size_t)(bn + r) * 2048 + k0 + u * 8]);
        }
    }
}

__global__ __launch_bounds__(256, 1) void gemm3_kernel(const float* __restrict__ bias,
                                                       float* __restrict__ out) {
    extern __shared__ __align__(1024) char smem[];
    const uint32_t sb = (uint32_t)__cvta_generic_to_shared(smem);
    const int tid  = threadIdx.x;
    const int wid  = tid >> 5, lane = tid & 31;
    const int bn   = blockIdx.x * 256;
    const int bm   = blockIdx.y * 128;
    const int wm   = (wid >> 2) * 64;   // 2 m-warps
    const int wn   = (wid & 3) * 64;    // 4 n-warps x 64

    float acc[4][8][4];
    #pragma unroll
    for (int i = 0; i < 4; ++i)
        #pragma unroll
        for (int j = 0; j < 8; ++j)
            #pragma unroll
            for (int q = 0; q < 4; ++q) acc[i][j][q] = 0.f;

    load_chunk3(sb, bm, bn, 0, tid);
    asm volatile("cp.async.commit_group;" ::: "memory");
    load_chunk3(sb + ST3, bm, bn, 64, tid);
    asm volatile("cp.async.commit_group;" ::: "memory");
    load_chunk3(sb + 2u * ST3, bm, bn, 128, tid);
    asm volatile("cp.async.commit_group;" ::: "memory");

    const int lrow = lane & 15;
    const int lcg  = (lane >> 4) * 16;

    for (int c = 0; c < NCHUNK3; ++c) {
        if (c + 2 < NCHUNK3)
            asm volatile("cp.async.wait_group 2;" ::: "memory");
        else if (c + 1 < NCHUNK3)
            asm volatile("cp.async.wait_group 1;" ::: "memory");
        else
            asm volatile("cp.async.wait_group 0;" ::: "memory");
        __syncthreads();
        if (c + 3 < NCHUNK3) {
            load_chunk3(sb + (uint32_t)((c + 3) & 3) * ST3, bm, bn,
                        (c + 3) * 64, tid);
            asm volatile("cp.async.commit_group;" ::: "memory");
        }

        const uint32_t cur = sb + (uint32_t)(c & 3) * ST3;
        #pragma unroll
        for (int ks = 0; ks < 4; ++ks) {
            const int kb = ks * 32 + lcg;
            uint32_t a[4][4], b[8][2];
            #pragma unroll
            for (int mt = 0; mt < 4; ++mt)
                ldm_x4(cur + SWZ128((uint32_t)((wm + mt * 16 + lrow) * 128 + kb)),
                       a[mt][0], a[mt][1], a[mt][2], a[mt][3]);
            #pragma unroll
            for (int q = 0; q < 4; ++q) {
                uint32_t r0, r1, r2, r3;
                ldm_x4(cur + B3_OFF +
                           SWZ128((uint32_t)((wn + q * 16 + lrow) * 128 + kb)),
                       r0, r1, r2, r3);
                b[2 * q][0] = r0;     b[2 * q][1] = r2;
                b[2 * q + 1][0] = r1; b[2 * q + 1][1] = r3;
            }
            #pragma unroll
            for (int mt = 0; mt < 4; ++mt)
                #pragma unroll
                for (int nt = 0; nt < 8; ++nt)
                    mma_f16(acc[mt][nt][0], acc[mt][nt][1],
                            acc[mt][nt][2], acc[mt][nt][3],
                            a[mt][0], a[mt][1], a[mt][2], a[mt][3],
                            b[nt][0], b[nt][1]);
        }
    }

    const int er = lane >> 2, ec = (lane & 3) * 2;
    #pragma unroll
    for (int mt = 0; mt < 4; ++mt) {
        #pragma unroll
        for (int nt = 0; nt < 8; ++nt) {
            const int n = bn + wn + nt * 8 + ec;
            const float bv0 = bias[n], bv1 = bias[n + 1];
            #pragma unroll
            for (int half = 0; half < 2; ++half) {
                const int m = bm + wm + mt * 16 + er + half * 8;
                float h0 = acc[mt][nt][half * 2 + 0] + bv0;
                float h1 = acc[mt][nt][half * 2 + 1] + bv1;
                float2 o2;
                o2.x = h0 > 0.f ? h0 : 0.01f * h0;
                o2.y = h1 > 0.f ? h1 : 0.01f * h1;
                *(float2*)&out[(size_t)m * 1024 + n] = o2;
            }
        }
    }
}

// ---------------------------------------------------------------------------
extern "C" void kernel_launch(void* const* d_in, const int* in_sizes, int n_in,
                              void* d_out, int out_size) {
    const float* base = (const float*)d_in[0];
    const int*   rois = (const int*)d_in[1];
    const float* w1   = (const float*)d_in[2];
    const float* b1   = (const float*)d_in[3];
    const float* w2   = (const float*)d_in[4];
    const float* b2   = (const float*)d_in[5];
    const float* wl   = (const float*)d_in[6];
    const float* bl   = (const float*)d_in[7];
    float* out = (float*)d_out;

    cudaFuncSetAttribute(zgemm_kernel, cudaFuncAttributeMaxDynamicSharedMemorySize,
                         ZG_SMEM);
    cudaFuncSetAttribute(gemm3_kernel, cudaFuncAttributeMaxDynamicSharedMemorySize,
                         GEMM_SMEM);

    prep_all<<<PREP_GRID, 256>>>(w1, b1, w2, base);
    zgemm_kernel<<<ZG_GRID, 256, ZG_SMEM>>>(rois, b2, wl);
    gemm3_kernel<<<dim3(1024 / 256, NSAMP / 128), 256, GEMM_SMEM>>>(bl, out);
}

// round 14
// speedup vs baseline: 1.0759x; 1.0759x over previous
#include <cuda_runtime.h>
#include <cuda_fp16.h>
#include <math.h>
#include <stdint.h>

// ---------------------------------------------------------------------------
//   base_feat: (32,256,512,4,4) f32 -> 8192 samples of (512,16)
//   rois:(8192,4) i32  w1:(512,256) b1:(256) w2:(256,128) b2:(128)
//   wl:(2048,1024) bl:(1024)  out:(8192,1024) f32
//
// feat[o,i,j] = b2[o] + S1[o]*(i,j odd) + Z[o,a,b]*((i,j) in {3,7}^2)
// Z = X(32768x512) @ W^T(128x512): zgemm reads base_feat DIRECTLY (center
//   extraction fused into A-tile load; g_X eliminated). B preloaded whole.
// out = leakyrelu(P(8192x2048) @ wl + bl): round-10 gemm3 (BN=256, 3-stage).
// fp16 mma.sync m16n8k16, fp32 accumulate.
// ---------------------------------------------------------------------------

#define NSAMP 8192

__device__ float g_S1[128];
__device__ unsigned short g_WZ[128 * 512];                // W^T [o][k]  fp16
__device__ unsigned short g_P[(size_t)NSAMP * 2048];      // P [n][o*16+cell] fp16
__device__ unsigned short g_WT[(size_t)1024 * 2048];      // wl^T [nn][k] fp16

#define SWZ128(off) ((off) ^ (((off) >> 3) & 0x70))

__device__ __forceinline__ unsigned short f2h(float x) {
    return __half_as_ushort(__float2half_rn(x));
}
__device__ __forceinline__ void cp16(uint32_t dst, const void* src) {
    asm volatile("cp.async.cg.shared.global [%0], [%1], 16;"
                 :: "r"(dst), "l"(__cvta_generic_to_global(src)) : "memory");
}
__device__ __forceinline__ void sts16(uint32_t addr, unsigned short v) {
    asm volatile("st.shared.u16 [%0], %1;" :: "r"(addr), "h"(v) : "memory");
}
__device__ __forceinline__ void ldm_x4(uint32_t addr, uint32_t& r0, uint32_t& r1,
                                       uint32_t& r2, uint32_t& r3) {
    asm volatile("ldmatrix.sync.aligned.m8n8.x4.shared.b16 {%0,%1,%2,%3}, [%4];"
                 : "=r"(r0), "=r"(r1), "=r"(r2), "=r"(r3) : "r"(addr));
}
__device__ __forceinline__ void mma_f16(float& d0, float& d1, float& d2, float& d3,
                                        uint32_t a0, uint32_t a1, uint32_t a2,
                                        uint32_t a3, uint32_t b0, uint32_t b1) {
    asm volatile("mma.sync.aligned.m16n8k16.row.col.f32.f16.f16.f32 "
                 "{%0,%1,%2,%3}, {%4,%5,%6,%7}, {%8,%9}, {%0,%1,%2,%3};"
                 : "+f"(d0), "+f"(d1), "+f"(d2), "+f"(d3)
                 : "r"(a0), "r"(a1), "r"(a2), "r"(a3), "r"(b0), "r"(b1));
}

// MMA over one [128][64] A tile (abase) x [128][64] B tile (bbase).
__device__ __forceinline__ void mma_block_ab(uint32_t abase, uint32_t bbase,
                                             float acc[4][4][4],
                                             int wm, int wn, int lane) {
    const int lrow = lane & 15;
    const int lcg  = (lane >> 4) * 16;
    #pragma unroll
    for (int ks = 0; ks < 4; ++ks) {
        const int kb = ks * 32 + lcg;
        uint32_t a[4][4], b[4][2];
        #pragma unroll
        for (int mt = 0; mt < 4; ++mt)
            ldm_x4(abase + SWZ128((uint32_t)((wm + mt * 16 + lrow) * 128 + kb)),
                   a[mt][0], a[mt][1], a[mt][2], a[mt][3]);
        #pragma unroll
        for (int q = 0; q < 2; ++q) {
            uint32_t r0, r1, r2, r3;
            ldm_x4(bbase + SWZ128((uint32_t)((wn + q * 16 + lrow) * 128 + kb)),
                   r0, r1, r2, r3);
            b[2 * q][0] = r0;     b[2 * q][1] = r2;
            b[2 * q + 1][0] = r1; b[2 * q + 1][1] = r3;
        }
        #pragma unroll
        for (int mt = 0; mt < 4; ++mt)
            #pragma unroll
            for (int nt = 0; nt < 4; ++nt)
                mma_f16(acc[mt][nt][0], acc[mt][nt][1],
                        acc[mt][nt][2], acc[mt][nt][3],
                        a[mt][0], a[mt][1], a[mt][2], a[mt][3],
                        b[nt][0], b[nt][1]);
    }
}

// ---------------------------------------------------------------------------
// Kernel 1 (producers): [0,256) W=w1@w2; [256] S1; [257,2305) wl transpose.
// ---------------------------------------------------------------------------
#define S1_B      256
#define WSP_B0    257
#define PREP_GRID 2305

__global__ __launch_bounds__(256) void prep_all(const float* __restrict__ w1,
                                                const float* __restrict__ b1,
                                                const float* __restrict__ w2,
                                                const float* __restrict__ wl) {
    __shared__ float w1s[2][256];
    __shared__ float t[32][33];
    const int b   = blockIdx.x;
    const int tid = threadIdx.x;

    if (b < S1_B) {
        for (int i = tid; i < 512; i += 256)
            ((float*)w1s)[i] = w1[(size_t)b * 512 + i];
        __syncthreads();
        const int kk = tid >> 7, o = tid & 127;
        float acc = 0.f;
        #pragma unroll 4
        for (int c = 0; c < 256; ++c)
            acc = fmaf(w1s[kk][c], w2[c * 128 + o], acc);
        g_WZ[o * 512 + b * 2 + kk] = f2h(acc);
    } else if (b == S1_B) {
        if (tid < 128) {
            float acc = 0.f;
            for (int c = 0; c < 256; ++c) acc = fmaf(b1[c], w2[c * 128 + tid], acc);
            g_S1[tid] = acc;
        }
    } else {
        const int w  = b - WSP_B0;
        const int n0 = (w & 31) * 32, k0 = (w >> 5) * 32;
        const int tx = tid & 31, ty = tid >> 5;   // 32 x 8
        #pragma unroll
        for (int j = 0; j < 4; ++j)
            t[ty + j * 8][tx] = wl[(size_t)(k0 + ty + j * 8) * 1024 + n0 + tx];
        __syncthreads();
        #pragma unroll
        for (int j = 0; j < 4; ++j)
            g_WT[(size_t)(n0 + ty + j * 8) * 2048 + k0 + tx] =
                f2h(t[tx][ty + j * 8]);
    }
}

// ---------------------------------------------------------------------------
// Kernel 2: zgemm (Z = X @ W^T) with fused center-extraction A-load and
// fused categorized max-pool epilogue.
// BM=128 (32 samples), BN=128, K=512, BK=64.
// SMEM: A double-buffer 2x16KB @0; B (all 8 chunks) 128KB @32KB; tail arrays.
// A loads: direct from base_feat (f32 -> fp16 regs->STS), double-buffered.
// ---------------------------------------------------------------------------
#define ZCHUNK    8
#define ZS_STRIDE 136
#define ZA_BUF    16384u
#define ZB_OFF    32768u
#define ZB_CHUNK  16384u
#define SM_ROIS   (ZB_OFF + 8u * ZB_CHUNK)      // 163840
#define SM_B2     (SM_ROIS + 512u)
#define SM_S1     (SM_B2 + 512u)
#define ZG_SMEM   (SM_S1 + 512u)

__global__ __launch_bounds__(256, 1) void zgemm_kernel(const int* __restrict__ rois,
                                                       const float* __restrict__ b2,
                                                       const float* __restrict__ base) {
    extern __shared__ __align__(1024) char smem[];
    const uint32_t sb = (uint32_t)__cvta_generic_to_shared(smem);
    const int tid  = threadIdx.x;
    const int wid  = tid >> 5, lane = tid & 31;
    const int n0   = blockIdx.x * 32;
    const int wm   = (wid >> 2) * 64;
    const int wn   = (wid & 3) * 32;

    int4*  rois_s = (int4*)(smem + SM_ROIS);
    float* b2s    = (float*)(smem + SM_B2);
    float* s1s    = (float*)(smem + SM_S1);
    if (tid < 32) rois_s[tid] = ((const int4*)rois)[n0 + tid];
    if (tid >= 128) { b2s[tid - 128] = b2[tid - 128]; s1s[tid - 128] = g_S1[tid - 128]; }

    // ---- preload ALL of B (g_WZ, 128 rows x 512 k, 8 chunks of [128][64]) ----
    #pragma unroll
    for (int it = 0; it < 32; ++it) {
        const int idx = tid + it * 256;          // 0..8191 (16B units)
        const int ck = idx >> 10;
        const int e  = idx & 1023;
        const int r  = e >> 3, u = e & 7;
        cp16(sb + ZB_OFF + (uint32_t)ck * ZB_CHUNK
                 + SWZ128((uint32_t)(r * 128 + u * 16)),
             &g_WZ[r * 512 + ck * 64 + u * 8]);
    }
    asm volatile("cp.async.commit_group;" ::: "memory");

    // ---- A chunk 0 into regs (pair p: sample n_local=pair>>6, k=pair&63) ----
    float4 ra[8], rb[8];
    #pragma unroll
    for (int p = 0; p < 8; ++p) {
        const int pair = tid + p * 256;
        const int nl = pair >> 6, k = pair & 63;
        const float4* s = (const float4*)(base + (size_t)(n0 + nl) * 8192 + k * 16);
        ra[p] = __ldcs(s + 1);   // f4..f7  -> .y=f5 .z=f6
        rb[p] = __ldcs(s + 2);   // f8..f11 -> .y=f9 .z=f10
    }
    asm volatile("cp.async.wait_group 0;" ::: "memory");   // B resident

    float acc[4][4][4];
    #pragma unroll
    for (int i = 0; i < 4; ++i)
        #pragma unroll
        for (int j = 0; j < 4; ++j)
            #pragma unroll
            for (int q = 0; q < 4; ++q) acc[i][j][q] = 0.f;

    for (int c = 0; c < ZCHUNK; ++c) {
        // STS chunk c from regs into buf[c&1] (rows m=4*nl+cc, col k)
        const uint32_t abuf = sb + (uint32_t)(c & 1) * ZA_BUF;
        #pragma unroll
        for (int p = 0; p < 8; ++p) {
            const int pair = tid + p * 256;
            const int nl = pair >> 6, k = pair & 63;
            const uint32_t b0 = (uint32_t)((4 * nl) * 128 + k * 2);
            sts16(abuf + SWZ128(b0 + 0 * 128), f2h(ra[p].y));
            sts16(abuf + SWZ128(b0 + 1 * 128), f2h(ra[p].z));
            sts16(abuf + SWZ128(b0 + 2 * 128), f2h(rb[p].y));
            sts16(abuf + SWZ128(b0 + 3 * 128), f2h(rb[p].z));
        }
        // issue LDG for chunk c+1 (latency hidden under MMA below)
        if (c + 1 < ZCHUNK) {
            const int k0 = (c + 1) * 64;
            #pragma unroll
            for (int p = 0; p < 8; ++p) {
                const int pair = tid + p * 256;
                const int nl = pair >> 6, k = pair & 63;
                const float4* s =
                    (const float4*)(base + (size_t)(n0 + nl) * 8192 + (k0 + k) * 16);
                ra[p] = __ldcs(s + 1);
                rb[p] = __ldcs(s + 2);
            }
        }
        __syncthreads();
        mma_block_ab(sb + (uint32_t)(c & 1) * ZA_BUF,
                     sb + ZB_OFF + (uint32_t)c * ZB_CHUNK, acc, wm, wn, lane);
    }
    __syncthreads();

    // stage Z tile to smem (f32, padded stride) — overlays A/B regions
    float* zs = (float*)smem;
    const int er = lane >> 2, ec = (lane & 3) * 2;
    #pragma unroll
    for (int mt = 0; mt < 4; ++mt)
        #pragma unroll
        for (int nt = 0; nt < 4; ++nt)
            #pragma unroll
            for (int half = 0; half < 2; ++half) {
                const int row = wm + mt * 16 + er + half * 8;
                const int col = wn + nt * 8 + ec;
                *(float2*)&zs[row * ZS_STRIDE + col] =
                    make_float2(acc[mt][nt][half * 2 + 0], acc[mt][nt][half * 2 + 1]);
            }
    __syncthreads();

    #pragma unroll 1
    for (int it = 0; it < 16; ++it) {
        const int pair = tid + it * 256;
        const int n = pair >> 7, o = pair & 127;
        const int4 rr = rois_s[n];
        const float b2o = b2s[o], s1o = s1s[o];
        const float z00 = zs[(4 * n + 0) * ZS_STRIDE + o];
        const float z01 = zs[(4 * n + 1) * ZS_STRIDE + o];
        const float z10 = zs[(4 * n + 2) * ZS_STRIDE + o];
        const float z11 = zs[(4 * n + 3) * ZS_STRIDE + o];

        int y0 = rr.x, x0 = rr.y;
        const int h = rr.z - rr.x, w = rr.w - rr.y;
        const bool inb = (rr.x >= 0 && rr.x < 11 && rr.y >= 0 && rr.y < 11 &&
                          rr.z >= 0 && rr.z < 11 && rr.w >= 0 && rr.w < 11);
        int cat;
        if      (inb && h == 4 && w == 4) cat = 0;
        else if (inb && h == 8 && w == 8) cat = 1;
        else if (inb && h == 4 && w == 8) cat = 2;
        else if (inb && h == 6 && w == 8) cat = 3;
        else { cat = 4; y0 = 1; x0 = 1; }

        auto feval = [&](int i, int j) -> float {
            float v = b2o;
            if ((i & 1) && (j & 1)) {
                v += s1o;
                const bool ia = (i == 3) || (i == 7);
                const bool ja = (j == 3) || (j == 7);
                if (ia && ja)
                    v += (i == 3) ? ((j == 3) ? z00 : z01)
                                  : ((j == 3) ? z10 : z11);
            }
            return v;
        };

        float cell[16];
        if (cat == 0) {
            for (int u = 0; u < 4; ++u)
                for (int v = 0; v < 4; ++v)
                    cell[u * 4 + v] = feval(y0 + u, x0 + v);
        } else if (cat == 1) {
            for (int u = 0; u < 4; ++u)
                for (int v = 0; v < 4; ++v) {
                    const int i0 = y0 + 2 * u, j0 = x0 + 2 * v;
                    cell[u * 4 + v] =
                        fmaxf(fmaxf(feval(i0, j0),     feval(i0, j0 + 1)),
                              fmaxf(feval(i0 + 1, j0), feval(i0 + 1, j0 + 1)));
                }
        } else if (cat == 2) {
            for (int u = 0; u < 4; ++u)
                for (int v = 0; v < 4; ++v) {
                    const int j0 = x0 + 2 * v;
                    cell[u * 4 + v] = fmaxf(feval(y0 + u, j0), feval(y0 + u, j0 + 1));
                }
        } else if (cat == 3) {
            for (int u = 0; u < 4; ++u)
                for (int v = 0; v < 4; ++v) {
                    const int j0 = x0 + 2 * v;
                    float m = -3.402823466e38f;
                    const int r0 = 2 * u - 1, r1 = 2 * u;
                    if (r0 >= 0) m = fmaxf(feval(y0 + r0, j0), feval(y0 + r0, j0 + 1));
                    if (r1 < 6)  m = fmaxf(m, fmaxf(feval(y0 + r1, j0),
                                                    feval(y0 + r1, j0 + 1)));
                    cell[u * 4 + v] = m;
                }
        } else {
            for (int u = 0; u < 4; ++u)
                for (int v = 0; v < 4; ++v) {
                    float m = -3.402823466e38f;
                    for (int di = 0; di < 3; ++di)
                        for (int dj = 0; dj < 3; ++dj)
                            m = fmaxf(m, feval(1 + 2 * u + di, 1 + 2 * v + dj));
                    cell[u * 4 + v] = m;
                }
        }

        __align__(16) unsigned short c16[16];
        #pragma unroll
        for (int i = 0; i < 16; ++i) c16[i] = f2h(cell[i]);
        uint4* pp = (uint4*)&g_P[(size_t)(n0 + n) * 2048 + o * 16];
        pp[0] = ((uint4*)c16)[0];
        pp[1] = ((uint4*)c16)[1];
    }
}

// ---------------------------------------------------------------------------
// Kernel 3: out = leakyrelu(P @ wl + bl), fp16 mma.  (round-10 best config)
// BM=128, BN=256, BK=64, K=2048, 3-stage (144KB smem).
// 8 warps as 2(m) x 4(n), warp tile 64x64.
// ---------------------------------------------------------------------------
#define NCHUNK3   32
#define ST3       49152u    // A 16KB + B 32KB
#define B3_OFF    16384u
#define GEMM_SMEM (3u * ST3)

__device__ __forceinline__ void load_chunk3(uint32_t sbase, int bm, int bn,
                                            int k0, int tid) {
    #pragma unroll
    for (int it = 0; it < 12; ++it) {
        const int g = tid + it * 256;            // 0..3071 (16B units)
        if (g < 1024) {                          // A: 128 rows x 128B
            const int r = g >> 3, u = g & 7;
            cp16(sbase + SWZ128((uint32_t)(r * 128 + u * 16)),
                 &g_P[(size_t)(bm + r) * 2048 + k0 + u * 8]);
        } else {                                 // B: 256 rows x 128B
            const int e = g - 1024;
            const int r = e >> 3, u = e & 7;
            cp16(sbase + B3_OFF + SWZ128((uint32_t)(r * 128 + u * 16)),
                 &g_WT[(size_t)(bn + r) * 2048 + k0 + u * 8]);
        }
    }
}

__global__ __launch_bounds__(256, 1) void gemm3_kernel(const float* __restrict__ bias,
                                                       float* __restrict__ out) {
    extern __shared__ __align__(1024) char smem[];
    const uint32_t sb = (uint32_t)__cvta_generic_to_shared(smem);
    const int tid  = threadIdx.x;
    const int wid  = tid >> 5, lane = tid & 31;
    const int bn   = blockIdx.x * 256;
    const int bm   = blockIdx.y * 128;
    const int wm   = (wid >> 2) * 64;   // 2 m-warps
    const int wn   = (wid & 3) * 64;    // 4 n-warps x 64

    float acc[4][8][4];
    #pragma unroll
    for (int i = 0; i < 4; ++i)
        #pragma unroll
        for (int j = 0; j < 8; ++j)
            #pragma unroll
            for (int q = 0; q < 4; ++q) acc[i][j][q] = 0.f;

    load_chunk3(sb, bm, bn, 0, tid);
    asm volatile("cp.async.commit_group;" ::: "memory");
    load_chunk3(sb + ST3, bm, bn, 64, tid);
    asm volatile("cp.async.commit_group;" ::: "memory");

    const int lrow = lane & 15;
    const int lcg  = (lane >> 4) * 16;

    for (int c = 0; c < NCHUNK3; ++c) {
        if (c + 1 < NCHUNK3)
            asm volatile("cp.async.wait_group 1;" ::: "memory");
        else
            asm volatile("cp.async.wait_group 0;" ::: "memory");
        __syncthreads();
        if (c + 2 < NCHUNK3) {
            load_chunk3(sb + (uint32_t)((c + 2) % 3) * ST3, bm, bn,
                        (c + 2) * 64, tid);
            asm volatile("cp.async.commit_group;" ::: "memory");
        }

        const uint32_t cur = sb + (uint32_t)(c % 3) * ST3;
        #pragma unroll
        for (int ks = 0; ks < 4; ++ks) {
            const int kb = ks * 32 + lcg;
            uint32_t a[4][4], b[8][2];
            #pragma unroll
            for (int mt = 0; mt < 4; ++mt)
                ldm_x4(cur + SWZ128((uint32_t)((wm + mt * 16 + lrow) * 128 + kb)),
                       a[mt][0], a[mt][1], a[mt][2], a[mt][3]);
            #pragma unroll
            for (int q = 0; q < 4; ++q) {
                uint32_t r0, r1, r2, r3;
                ldm_x4(cur + B3_OFF +
                           SWZ128((uint32_t)((wn + q * 16 + lrow) * 128 + kb)),
                       r0, r1, r2, r3);
                b[2 * q][0] = r0;     b[2 * q][1] = r2;
                b[2 * q + 1][0] = r1; b[2 * q + 1][1] = r3;
            }
            #pragma unroll
            for (int mt = 0; mt < 4; ++mt)
                #pragma unroll
                for (int nt = 0; nt < 8; ++nt)
                    mma_f16(acc[mt][nt][0], acc[mt][nt][1],
                            acc[mt][nt][2], acc[mt][nt][3],
                            a[mt][0], a[mt][1], a[mt][2], a[mt][3],
                            b[nt][0], b[nt][1]);
        }
    }

    const int er = lane >> 2, ec = (lane & 3) * 2;
    #pragma unroll
    for (int mt = 0; mt < 4; ++mt) {
        #pragma unroll
        for (int nt = 0; nt < 8; ++nt) {
            const int n = bn + wn + nt * 8 + ec;
            const float bv0 = bias[n], bv1 = bias[n + 1];
            #pragma unroll
            for (int half = 0; half < 2; ++half) {
                const int m = bm + wm + mt * 16 + er + half * 8;
                float h0 = acc[mt][nt][half * 2 + 0] + bv0;
                float h1 = acc[mt][nt][half * 2 + 1] + bv1;
                float2 o2;
                o2.x = h0 > 0.f ? h0 : 0.01f * h0;
                o2.y = h1 > 0.f ? h1 : 0.01f * h1;
                *(float2*)&out[(size_t)m * 1024 + n] = o2;
            }
        }
    }
}

// ---------------------------------------------------------------------------
extern "C" void kernel_launch(void* const* d_in, const int* in_sizes, int n_in,
                              void* d_out, int out_size) {
    const float* base = (const float*)d_in[0];
    const int*   rois = (const int*)d_in[1];
    const float* w1   = (const float*)d_in[2];
    const float* b1   = (const float*)d_in[3];
    const float* w2   = (const float*)d_in[4];
    const float* b2   = (const float*)d_in[5];
    const float* wl   = (const float*)d_in[6];
    const float* bl   = (const float*)d_in[7];
    float* out = (float*)d_out;

    cudaFuncSetAttribute(zgemm_kernel, cudaFuncAttributeMaxDynamicSharedMemorySize,
                         ZG_SMEM);
    cudaFuncSetAttribute(gemm3_kernel, cudaFuncAttributeMaxDynamicSharedMemorySize,
                         GEMM_SMEM);

    prep_all<<<PREP_GRID, 256>>>(w1, b1, w2, wl);
    zgemm_kernel<<<NSAMP / 32, 256, ZG_SMEM>>>(rois, b2, base);
    gemm3_kernel<<<dim3(1024 / 256, NSAMP / 128), 256, GEMM_SMEM>>>(bl, out);
}

// round 15
// speedup vs baseline: 1.0845x; 1.0080x over previous
#include <cuda_runtime.h>
#include <cuda_fp16.h>
#include <math.h>
#include <stdint.h>

// ---------------------------------------------------------------------------
//   base_feat: (32,256,512,4,4) f32 -> 8192 samples of (512,16)
//   rois:(8192,4) i32  w1:(512,256) b1:(256) w2:(256,128) b2:(128)
//   wl:(2048,1024) bl:(1024)  out:(8192,1024) f32
//
// feat[o,i,j] = b2[o] + S1[o]*(i,j odd) + Z[o,a,b]*((i,j) in {3,7}^2)
// Z = X(32768x512) @ W^T(128x512): zgemm reads base_feat DIRECTLY (center
//   extraction fused into A-tile load). B (g_WZ) preloaded whole per block.
// out = leakyrelu(P(8192x2048) @ wl + bl): BN=256, 3-stage fp16 mma.
// prep: W-GEMM restructured as 32 fat blocks w/ smem-staged w2 (latency fix).
// ---------------------------------------------------------------------------

#define NSAMP 8192

__device__ float g_S1[128];
__device__ unsigned short g_WZ[128 * 512];                // W^T [o][k]  fp16
__device__ unsigned short g_P[(size_t)NSAMP * 2048];      // P [n][o*16+cell] fp16
__device__ unsigned short g_WT[(size_t)1024 * 2048];      // wl^T [nn][k] fp16

#define SWZ128(off) ((off) ^ (((off) >> 3) & 0x70))

__device__ __forceinline__ unsigned short f2h(float x) {
    return __half_as_ushort(__float2half_rn(x));
}
__device__ __forceinline__ void cp16(uint32_t dst, const void* src) {
    asm volatile("cp.async.cg.shared.global [%0], [%1], 16;"
                 :: "r"(dst), "l"(__cvta_generic_to_global(src)) : "memory");
}
__device__ __forceinline__ void sts16(uint32_t addr, unsigned short v) {
    asm volatile("st.shared.u16 [%0], %1;" :: "r"(addr), "h"(v) : "memory");
}
__device__ __forceinline__ void ldm_x4(uint32_t addr, uint32_t& r0, uint32_t& r1,
                                       uint32_t& r2, uint32_t& r3) {
    asm volatile("ldmatrix.sync.aligned.m8n8.x4.shared.b16 {%0,%1,%2,%3}, [%4];"
                 : "=r"(r0), "=r"(r1), "=r"(r2), "=r"(r3) : "r"(addr));
}
__device__ __forceinline__ void mma_f16(float& d0, float& d1, float& d2, float& d3,
                                        uint32_t a0, uint32_t a1, uint32_t a2,
                                        uint32_t a3, uint32_t b0, uint32_t b1) {
    asm volatile("mma.sync.aligned.m16n8k16.row.col.f32.f16.f16.f32 "
                 "{%0,%1,%2,%3}, {%4,%5,%6,%7}, {%8,%9}, {%0,%1,%2,%3};"
                 : "+f"(d0), "+f"(d1), "+f"(d2), "+f"(d3)
                 : "r"(a0), "r"(a1), "r"(a2), "r"(a3), "r"(b0), "r"(b1));
}

// MMA over one [128][64] A tile (abase) x [128][64] B tile (bbase).
__device__ __forceinline__ void mma_block_ab(uint32_t abase, uint32_t bbase,
                                             float acc[4][4][4],
                                             int wm, int wn, int lane) {
    const int lrow = lane & 15;
    const int lcg  = (lane >> 4) * 16;
    #pragma unroll
    for (int ks = 0; ks < 4; ++ks) {
        const int kb = ks * 32 + lcg;
        uint32_t a[4][4], b[4][2];
        #pragma unroll
        for (int mt = 0; mt < 4; ++mt)
            ldm_x4(abase + SWZ128((uint32_t)((wm + mt * 16 + lrow) * 128 + kb)),
                   a[mt][0], a[mt][1], a[mt][2], a[mt][3]);
        #pragma unroll
        for (int q = 0; q < 2; ++q) {
            uint32_t r0, r1, r2, r3;
            ldm_x4(bbase + SWZ128((uint32_t)((wn + q * 16 + lrow) * 128 + kb)),
                   r0, r1, r2, r3);
            b[2 * q][0] = r0;     b[2 * q][1] = r2;
            b[2 * q + 1][0] = r1; b[2 * q + 1][1] = r3;
        }
        #pragma unroll
        for (int mt = 0; mt < 4; ++mt)
            #pragma unroll
            for (int nt = 0; nt < 4; ++nt)
                mma_f16(acc[mt][nt][0], acc[mt][nt][1],
                        acc[mt][nt][2], acc[mt][nt][3],
                        a[mt][0], a[mt][1], a[mt][2], a[mt][3],
                        b[nt][0], b[nt][1]);
    }
}

// ---------------------------------------------------------------------------
// Kernel 1 (producers):
//   [0,32):    W = w1 @ w2, 16 k-rows/block, w1+w2-slab in smem (cp.async)
//   [32]:      S1 = b1 @ w2
//   [33,2081): transpose wl -> fp16 g_WT (32x32 tiles)
// ---------------------------------------------------------------------------
#define W_BLKS    32
#define S1_B      32
#define WSP_B0    33
#define PREP_GRID 2081

__global__ __launch_bounds__(256) void prep_all(const float* __restrict__ w1,
                                                const float* __restrict__ b1,
                                                const float* __restrict__ w2,
                                                const float* __restrict__ wl) {
    const int b   = blockIdx.x;
    const int tid = threadIdx.x;

    if (b < W_BLKS) {
        __shared__ float w1s[16][256];    // 16KB
        __shared__ float w2s[64][128];    // 32KB slab
        const uint32_t w2sb = (uint32_t)__cvta_generic_to_shared(w2s);

        // stage w1 rows [16b, 16b+16) via cp.async (16KB)
        {
            const uint32_t w1sb = (uint32_t)__cvta_generic_to_shared(w1s);
            #pragma unroll
            for (int i = 0; i < 4; ++i) {
                const int e = tid + i * 256;          // 0..1023 float4s
                cp16(w1sb + e * 16, w1 + (size_t)b * 4096 + e * 4);
            }
            asm volatile("cp.async.commit_group;" ::: "memory");
        }

        const int o  = tid & 127;
        const int kg = tid >> 7;          // 0..1 -> rows kg*8..kg*8+7
        float acc[8];
        #pragma unroll
        for (int r = 0; r < 8; ++r) acc[r] = 0.f;

        for (int slab = 0; slab < 4; ++slab) {
            // stage w2 rows [slab*64, slab*64+64) (32KB)
            #pragma unroll
            for (int i = 0; i < 8; ++i) {
                const int e = tid + i * 256;          // 0..2047 float4s
                cp16(w2sb + e * 16, w2 + (size_t)slab * 8192 + e * 4);
            }
            asm volatile("cp.async.commit_group;" ::: "memory");
            asm volatile("cp.async.wait_group 0;" ::: "memory");
            __syncthreads();

            #pragma unroll 4
            for (int c = 0; c < 64; ++c) {
                const float wv = w2s[c][o];
                #pragma unroll
                for (int r = 0; r < 8; ++r)
                    acc[r] = fmaf(w1s[kg * 8 + r][slab * 64 + c], wv, acc[r]);
            }
            __syncthreads();   // before next slab overwrite
        }

        #pragma unroll
        for (int r = 0; r < 8; ++r)
            g_WZ[o * 512 + b * 16 + kg * 8 + r] = f2h(acc[r]);
    } else if (b == S1_B) {
        if (tid < 128) {
            float acc = 0.f;
            for (int c = 0; c < 256; ++c) acc = fmaf(b1[c], w2[c * 128 + tid], acc);
            g_S1[tid] = acc;
        }
    } else {
        __shared__ float t[32][33];
        const int w  = b - WSP_B0;
        const int n0 = (w & 31) * 32, k0 = (w >> 5) * 32;
        const int tx = tid & 31, ty = tid >> 5;   // 32 x 8
        #pragma unroll
        for (int j = 0; j < 4; ++j)
            t[ty + j * 8][tx] = wl[(size_t)(k0 + ty + j * 8) * 1024 + n0 + tx];
        __syncthreads();
        #pragma unroll
        for (int j = 0; j < 4; ++j)
            g_WT[(size_t)(n0 + ty + j * 8) * 2048 + k0 + tx] =
                f2h(t[tx][ty + j * 8]);
    }
}

// ---------------------------------------------------------------------------
// Kernel 2: zgemm (Z = X @ W^T) with fused center-extraction A-load and
// fused categorized max-pool epilogue.
// BM=128 (32 samples), BN=128, K=512, BK=64.
// SMEM: A double-buffer 2x16KB @0; B (all 8 chunks) 128KB @32KB; tail arrays.
// ---------------------------------------------------------------------------
#define ZCHUNK    8
#define ZS_STRIDE 136
#define ZA_BUF    16384u
#define ZB_OFF    32768u
#define ZB_CHUNK  16384u
#define SM_ROIS   (ZB_OFF + 8u * ZB_CHUNK)      // 163840
#define SM_B2     (SM_ROIS + 512u)
#define SM_S1     (SM_B2 + 512u)
#define ZG_SMEM   (SM_S1 + 512u)

__global__ __launch_bounds__(256, 1) void zgemm_kernel(const int* __restrict__ rois,
                                                       const float* __restrict__ b2,
                                                       const float* __restrict__ base) {
    extern __shared__ __align__(1024) char smem[];
    const uint32_t sb = (uint32_t)__cvta_generic_to_shared(smem);
    const int tid  = threadIdx.x;
    const int wid  = tid >> 5, lane = tid & 31;
    const int n0   = blockIdx.x * 32;
    const int wm   = (wid >> 2) * 64;
    const int wn   = (wid & 3) * 32;

    int4*  rois_s = (int4*)(smem + SM_ROIS);
    float* b2s    = (float*)(smem + SM_B2);
    float* s1s    = (float*)(smem + SM_S1);
    if (tid < 32) rois_s[tid] = ((const int4*)rois)[n0 + tid];
    if (tid >= 128) { b2s[tid - 128] = b2[tid - 128]; s1s[tid - 128] = g_S1[tid - 128]; }

    // ---- preload ALL of B (g_WZ, 128 rows x 512 k, 8 chunks of [128][64]) ----
    #pragma unroll
    for (int it = 0; it < 32; ++it) {
        const int idx = tid + it * 256;          // 0..8191 (16B units)
        const int ck = idx >> 10;
        const int e  = idx & 1023;
        const int r  = e >> 3, u = e & 7;
        cp16(sb + ZB_OFF + (uint32_t)ck * ZB_CHUNK
                 + SWZ128((uint32_t)(r * 128 + u * 16)),
             &g_WZ[r * 512 + ck * 64 + u * 8]);
    }
    asm volatile("cp.async.commit_group;" ::: "memory");

    // ---- A chunk 0 into regs (pair p: sample n_local=pair>>6, k=pair&63) ----
    float4 ra[8], rb[8];
    #pragma unroll
    for (int p = 0; p < 8; ++p) {
        const int pair = tid + p * 256;
        const int nl = pair >> 6, k = pair & 63;
        const float4* s = (const float4*)(base + (size_t)(n0 + nl) * 8192 + k * 16);
        ra[p] = __ldcs(s + 1);   // f4..f7  -> .y=f5 .z=f6
        rb[p] = __ldcs(s + 2);   // f8..f11 -> .y=f9 .z=f10
    }
    asm volatile("cp.async.wait_group 0;" ::: "memory");   // B resident

    float acc[4][4][4];
    #pragma unroll
    for (int i = 0; i < 4; ++i)
        #pragma unroll
        for (int j = 0; j < 4; ++j)
            #pragma unroll
            for (int q = 0; q < 4; ++q) acc[i][j][q] = 0.f;

    for (int c = 0; c < ZCHUNK; ++c) {
        const uint32_t abuf = sb + (uint32_t)(c & 1) * ZA_BUF;
        #pragma unroll
        for (int p = 0; p < 8; ++p) {
            const int pair = tid + p * 256;
            const int nl = pair >> 6, k = pair & 63;
            const uint32_t b0 = (uint32_t)((4 * nl) * 128 + k * 2);
            sts16(abuf + SWZ128(b0 + 0 * 128), f2h(ra[p].y));
            sts16(abuf + SWZ128(b0 + 1 * 128), f2h(ra[p].z));
            sts16(abuf + SWZ128(b0 + 2 * 128), f2h(rb[p].y));
            sts16(abuf + SWZ128(b0 + 3 * 128), f2h(rb[p].z));
        }
        if (c + 1 < ZCHUNK) {
            const int k0 = (c + 1) * 64;
            #pragma unroll
            for (int p = 0; p < 8; ++p) {
                const int pair = tid + p * 256;
                const int nl = pair >> 6, k = pair & 63;
                const float4* s =
                    (const float4*)(base + (size_t)(n0 + nl) * 8192 + (k0 + k) * 16);
                ra[p] = __ldcs(s + 1);
                rb[p] = __ldcs(s + 2);
            }
        }
        __syncthreads();
        mma_block_ab(sb + (uint32_t)(c & 1) * ZA_BUF,
                     sb + ZB_OFF + (uint32_t)c * ZB_CHUNK, acc, wm, wn, lane);
    }
    __syncthreads();

    // stage Z tile to smem (f32, padded stride) — overlays A/B regions
    float* zs = (float*)smem;
    const int er = lane >> 2, ec = (lane & 3) * 2;
    #pragma unroll
    for (int mt = 0; mt < 4; ++mt)
        #pragma unroll
        for (int nt = 0; nt < 4; ++nt)
            #pragma unroll
            for (int half = 0; half < 2; ++half) {
                const int row = wm + mt * 16 + er + half * 8;
                const int col = wn + nt * 8 + ec;
                *(float2*)&zs[row * ZS_STRIDE + col] =
                    make_float2(acc[mt][nt][half * 2 + 0], acc[mt][nt][half * 2 + 1]);
            }
    __syncthreads();

    #pragma unroll 1
    for (int it = 0; it < 16; ++it) {
        const int pair = tid + it * 256;
        const int n = pair >> 7, o = pair & 127;
        const int4 rr = rois_s[n];
        const float b2o = b2s[o], s1o = s1s[o];
        const float z00 = zs[(4 * n + 0) * ZS_STRIDE + o];
        const float z01 = zs[(4 * n + 1) * ZS_STRIDE + o];
        const float z10 = zs[(4 * n + 2) * ZS_STRIDE + o];
        const float z11 = zs[(4 * n + 3) * ZS_STRIDE + o];

        int y0 = rr.x, x0 = rr.y;
        const int h = rr.z - rr.x, w = rr.w - rr.y;
        const bool inb = (rr.x >= 0 && rr.x < 11 && rr.y >= 0 && rr.y < 11 &&
                          rr.z >= 0 && rr.z < 11 && rr.w >= 0 && rr.w < 11);
        int cat;
        if      (inb && h == 4 && w == 4) cat = 0;
        else if (inb && h == 8 && w == 8) cat = 1;
        else if (inb && h == 4 && w == 8) cat = 2;
        else if (inb && h == 6 && w == 8) cat = 3;
        else { cat = 4; y0 = 1; x0 = 1; }

        auto feval = [&](int i, int j) -> float {
            float v = b2o;
            if ((i & 1) && (j & 1)) {
                v += s1o;
                const bool ia = (i == 3) || (i == 7);
                const bool ja = (j == 3) || (j == 7);
                if (ia && ja)
                    v += (i == 3) ? ((j == 3) ? z00 : z01)
                                  : ((j == 3) ? z10 : z11);
            }
            return v;
        };

        float cell[16];
        if (cat == 0) {
            for (int u = 0; u < 4; ++u)
                for (int v = 0; v < 4; ++v)
                    cell[u * 4 + v] = feval(y0 + u, x0 + v);
        } else if (cat == 1) {
            for (int u = 0; u < 4; ++u)
                for (int v = 0; v < 4; ++v) {
                    const int i0 = y0 + 2 * u, j0 = x0 + 2 * v;
                    cell[u * 4 + v] =
                        fmaxf(fmaxf(feval(i0, j0),     feval(i0, j0 + 1)),
                              fmaxf(feval(i0 + 1, j0), feval(i0 + 1, j0 + 1)));
                }
        } else if (cat == 2) {
            for (int u = 0; u < 4; ++u)
                for (int v = 0; v < 4; ++v) {
                    const int j0 = x0 + 2 * v;
                    cell[u * 4 + v] = fmaxf(feval(y0 + u, j0), feval(y0 + u, j0 + 1));
                }
        } else if (cat == 3) {
            for (int u = 0; u < 4; ++u)
                for (int v = 0; v < 4; ++v) {
                    const int j0 = x0 + 2 * v;
                    float m = -3.402823466e38f;
                    const int r0 = 2 * u - 1, r1 = 2 * u;
                    if (r0 >= 0) m = fmaxf(feval(y0 + r0, j0), feval(y0 + r0, j0 + 1));
                    if (r1 < 6)  m = fmaxf(m, fmaxf(feval(y0 + r1, j0),
                                                    feval(y0 + r1, j0 + 1)));
                    cell[u * 4 + v] = m;
                }
        } else {
            for (int u = 0; u < 4; ++u)
                for (int v = 0; v < 4; ++v) {
                    float m = -3.402823466e38f;
                    for (int di = 0; di < 3; ++di)
                        for (int dj = 0; dj < 3; ++dj)
                            m = fmaxf(m, feval(1 + 2 * u + di, 1 + 2 * v + dj));
                    cell[u * 4 + v] = m;
                }
        }

        __align__(16) unsigned short c16[16];
        #pragma unroll
        for (int i = 0; i < 16; ++i) c16[i] = f2h(cell[i]);
        uint4* pp = (uint4*)&g_P[(size_t)(n0 + n) * 2048 + o * 16];
        pp[0] = ((uint4*)c16)[0];
        pp[1] = ((uint4*)c16)[1];
    }
}

// ---------------------------------------------------------------------------
// Kernel 3: out = leakyrelu(P @ wl + bl), fp16 mma.  (round-10 best config)
// BM=128, BN=256, BK=64, K=2048, 3-stage (144KB smem).
// 8 warps as 2(m) x 4(n), warp tile 64x64.
// ---------------------------------------------------------------------------
#define NCHUNK3   32
#define ST3       49152u    // A 16KB + B 32KB
#define B3_OFF    16384u
#define GEMM_SMEM (3u * ST3)

__device__ __forceinline__ void load_chunk3(uint32_t sbase, int bm, int bn,
                                            int k0, int tid) {
    #pragma unroll
    for (int it = 0; it < 12; ++it) {
        const int g = tid + it * 256;            // 0..3071 (16B units)
        if (g < 1024) {                          // A: 128 rows x 128B
            const int r = g >> 3, u = g & 7;
            cp16(sbase + SWZ128((uint32_t)(r * 128 + u * 16)),
                 &g_P[(size_t)(bm + r) * 2048 + k0 + u * 8]);
        } else {                                 // B: 256 rows x 128B
            const int e = g - 1024;
            const int r = e >> 3, u = e & 7;
            cp16(sbase + B3_OFF + SWZ128((uint32_t)(r * 128 + u * 16)),
                 &g_WT[(size_t)(bn + r) * 2048 + k0 + u * 8]);
        }
    }
}

__global__ __launch_bounds__(256, 1) void gemm3_kernel(const float* __restrict__ bias,
                                                       float* __restrict__ out) {
    extern __shared__ __align__(1024) char smem[];
    const uint32_t sb = (uint32_t)__cvta_generic_to_shared(smem);
    const int tid  = threadIdx.x;
    const int wid  = tid >> 5, lane = tid & 31;
    const int bn   = blockIdx.x * 256;
    const int bm   = blockIdx.y * 128;
    const int wm   = (wid >> 2) * 64;   // 2 m-warps
    const int wn   = (wid & 3) * 64;    // 4 n-warps x 64

    float acc[4][8][4];
    #pragma unroll
    for (int i = 0; i < 4; ++i)
        #pragma unroll
        for (int j = 0; j < 8; ++j)
            #pragma unroll
            for (int q = 0; q < 4; ++q) acc[i][j][q] = 0.f;

    load_chunk3(sb, bm, bn, 0, tid);
    asm volatile("cp.async.commit_group;" ::: "memory");
    load_chunk3(sb + ST3, bm, bn, 64, tid);
    asm volatile("cp.async.commit_group;" ::: "memory");

    const int lrow = lane & 15;
    const int lcg  = (lane >> 4) * 16;

    for (int c = 0; c < NCHUNK3; ++c) {
        if (c + 1 < NCHUNK3)
            asm volatile("cp.async.wait_group 1;" ::: "memory");
        else
            asm volatile("cp.async.wait_group 0;" ::: "memory");
        __syncthreads();
        if (c + 2 < NCHUNK3) {
            load_chunk3(sb + (uint32_t)((c + 2) % 3) * ST3, bm, bn,
                        (c + 2) * 64, tid);
            asm volatile("cp.async.commit_group;" ::: "memory");
        }

        const uint32_t cur = sb + (uint32_t)(c % 3) * ST3;
        #pragma unroll
        for (int ks = 0; ks < 4; ++ks) {
            const int kb = ks * 32 + lcg;
            uint32_t a[4][4], b[8][2];
            #pragma unroll
            for (int mt = 0; mt < 4; ++mt)
                ldm_x4(cur + SWZ128((uint32_t)((wm + mt * 16 + lrow) * 128 + kb)),
                       a[mt][0], a[mt][1], a[mt][2], a[mt][3]);
            #pragma unroll
            for (int q = 0; q < 4; ++q) {
                uint32_t r0, r1, r2, r3;
                ldm_x4(cur + B3_OFF +
                           SWZ128((uint32_t)((wn + q * 16 + lrow) * 128 + kb)),
                       r0, r1, r2, r3);
                b[2 * q][0] = r0;     b[2 * q][1] = r2;
                b[2 * q + 1][0] = r1; b[2 * q + 1][1] = r3;
            }
            #pragma unroll
            for (int mt = 0; mt < 4; ++mt)
                #pragma unroll
                for (int nt = 0; nt < 8; ++nt)
                    mma_f16(acc[mt][nt][0], acc[mt][nt][1],
                            acc[mt][nt][2], acc[mt][nt][3],
                            a[mt][0], a[mt][1], a[mt][2], a[mt][3],
                            b[nt][0], b[nt][1]);
        }
    }

    const int er = lane >> 2, ec = (lane & 3) * 2;
    #pragma unroll
    for (int mt = 0; mt < 4; ++mt) {
        #pragma unroll
        for (int nt = 0; nt < 8; ++nt) {
            const int n = bn + wn + nt * 8 + ec;
            const float bv0 = bias[n], bv1 = bias[n + 1];
            #pragma unroll
            for (int half = 0; half < 2; ++half) {
                const int m = bm + wm + mt * 16 + er + half * 8;
                float h0 = acc[mt][nt][half * 2 + 0] + bv0;
                float h1 = acc[mt][nt][half * 2 + 1] + bv1;
                float2 o2;
                o2.x = h0 > 0.f ? h0 : 0.01f * h0;
                o2.y = h1 > 0.f ? h1 : 0.01f * h1;
                *(float2*)&out[(size_t)m * 1024 + n] = o2;
            }
        }
    }
}

// ---------------------------------------------------------------------------
extern "C" void kernel_launch(void* const* d_in, const int* in_sizes, int n_in,
                              void* d_out, int out_size) {
    const float* base = (const float*)d_in[0];
    const int*   rois = (const int*)d_in[1];
    const float* w1   = (const float*)d_in[2];
    const float* b1   = (const float*)d_in[3];
    const float* w2   = (const float*)d_in[4];
    const float* b2   = (const float*)d_in[5];
    const float* wl   = (const float*)d_in[6];
    const float* bl   = (const float*)d_in[7];
    float* out = (float*)d_out;

    cudaFuncSetAttribute(zgemm_kernel, cudaFuncAttributeMaxDynamicSharedMemorySize,
                         ZG_SMEM);
    cudaFuncSetAttribute(gemm3_kernel, cudaFuncAttributeMaxDynamicSharedMemorySize,
                         GEMM_SMEM);

    prep_all<<<PREP_GRID, 256>>>(w1, b1, w2, wl);
    zgemm_kernel<<<NSAMP / 32, 256, ZG_SMEM>>>(rois, b2, base);
    gemm3_kernel<<<dim3(1024 / 256, NSAMP / 128), 256, GEMM_SMEM>>>(bl, out);
}